// round 1
// baseline (speedup 1.0000x reference)
#include <cuda_runtime.h>
#include <math.h>

#define Bdim 2
#define Ldim 2048
#define Edim 1024
#define Hdim 16
#define Ddim 64
#define NROWS (Bdim * Ldim)  // 4096

// Scratch (allocation-free rule: __device__ globals)
__device__ float g_proj[3][(size_t)NROWS * Edim];  // q, k, v projections, (B*L, E) row-major
__device__ float g_ho[Bdim * Edim];                // per-(b,h,d) accumulated head output

// ======================================================================
// Projection GEMM: C = X @ W^T   (X: 4096x1024, W: 1024x1024, both row-major)
// Tiles: 128x128x32, 256 threads, 8x8 per thread, transposed smem tiles.
// blockIdx.z selects (Q,Wq)->g_proj[0], (K,Wk)->g_proj[1], (V,Wv)->g_proj[2]
// ======================================================================
#define PBK 32
#define PST 136  // 128 + 8 pad; 136*4 bytes = 16-byte aligned rows

__global__ void __launch_bounds__(256) proj_kernel(
    const float* __restrict__ Q, const float* __restrict__ K, const float* __restrict__ V,
    const float* __restrict__ Wq, const float* __restrict__ Wk, const float* __restrict__ Wv)
{
    __shared__ float At[PBK][PST];
    __shared__ float Bt[PBK][PST];

    const int z = blockIdx.z;
    const float* __restrict__ X = (z == 0) ? Q : ((z == 1) ? K : V);
    const float* __restrict__ W = (z == 0) ? Wq : ((z == 1) ? Wk : Wv);
    float* __restrict__ C = g_proj[z];

    const int tid = threadIdx.x;
    const int tx = tid & 15;
    const int ty = tid >> 4;
    const int m0 = blockIdx.x * 128;
    const int n0 = blockIdx.y * 128;

    float acc[8][8];
#pragma unroll
    for (int i = 0; i < 8; i++)
#pragma unroll
        for (int j = 0; j < 8; j++) acc[i][j] = 0.f;

    for (int k0 = 0; k0 < Edim; k0 += PBK) {
        // Load 128x32 tiles of X and W, stored transposed (k-major) for float4 LDS
#pragma unroll
        for (int it = 0; it < 4; it++) {
            int idx = tid + it * 256;  // 0..1023
            int row = idx >> 3;        // 0..127
            int kq = idx & 7;          // 0..7  (k quad)
            float4 va = *(const float4*)&X[(size_t)(m0 + row) * Edim + k0 + kq * 4];
            At[kq * 4 + 0][row] = va.x;
            At[kq * 4 + 1][row] = va.y;
            At[kq * 4 + 2][row] = va.z;
            At[kq * 4 + 3][row] = va.w;
            float4 vb = *(const float4*)&W[(size_t)(n0 + row) * Edim + k0 + kq * 4];
            Bt[kq * 4 + 0][row] = vb.x;
            Bt[kq * 4 + 1][row] = vb.y;
            Bt[kq * 4 + 2][row] = vb.z;
            Bt[kq * 4 + 3][row] = vb.w;
        }
        __syncthreads();

#pragma unroll 8
        for (int k = 0; k < PBK; k++) {
            float a[8], b[8];
            *(float4*)&a[0] = *(const float4*)&At[k][ty * 8];
            *(float4*)&a[4] = *(const float4*)&At[k][ty * 8 + 4];
            *(float4*)&b[0] = *(const float4*)&Bt[k][tx * 8];
            *(float4*)&b[4] = *(const float4*)&Bt[k][tx * 8 + 4];
#pragma unroll
            for (int i = 0; i < 8; i++)
#pragma unroll
                for (int j = 0; j < 8; j++) acc[i][j] = fmaf(a[i], b[j], acc[i][j]);
        }
        __syncthreads();
    }

#pragma unroll
    for (int i = 0; i < 8; i++) {
        int row = m0 + ty * 8 + i;
        float4 c0 = make_float4(acc[i][0], acc[i][1], acc[i][2], acc[i][3]);
        float4 c1 = make_float4(acc[i][4], acc[i][5], acc[i][6], acc[i][7]);
        *(float4*)&C[(size_t)row * Edim + n0 + tx * 8] = c0;
        *(float4*)&C[(size_t)row * Edim + n0 + tx * 8 + 4] = c1;
    }
}

// ======================================================================
// Zero the head-output accumulator
// ======================================================================
__global__ void zero_ho_kernel()
{
    int i = blockIdx.x * blockDim.x + threadIdx.x;
    if (i < Bdim * Edim) g_ho[i] = 0.f;
}

// ======================================================================
// Flash-style L2-distance attention, one (b,h) per blockIdx.y,
// 64 query rows per block. Online softmax of  s = -sqrt(max(q2+k2-2qk,0)).
// Because the reference sums O over query positions, each block reduces its
// O tile (after /Z) to 64 column sums and atomicAdds into g_ho[b, h*64+d].
// ======================================================================
#define AST 76  // padded stride for 64-wide transposed tiles (76*4 = 16B-aligned rows)
#define ASM_FLOATS (64 * AST * 2 + 64 * 64 + 192)
#define ASM_BYTES (ASM_FLOATS * 4)

__global__ void __launch_bounds__(256) attn_kernel()
{
    extern __shared__ float sm[];
    float* qt = sm;                // [64 d][AST r]  q tile transposed
    float* kt = qt + 64 * AST;     // [64 d][AST j]  k tile transposed; reused as Pt[j][r]
    float* vs = kt + 64 * AST;     // [64 j][64 c]
    float* q2s = vs + 64 * 64;     // [64]
    float* k2s = q2s + 64;         // [64]
    float* csum = k2s + 64;        // [64]

    const int tid = threadIdx.x;
    const int tx = tid & 15;   // 4 columns tx*4..tx*4+3
    const int ty = tid >> 4;   // 4 rows    ty*4..ty*4+3
    const int bh = blockIdx.y;
    const int b = bh >> 4;
    const int h = bh & 15;
    const int r0 = blockIdx.x * 64;

    const float* __restrict__ gq = g_proj[0];
    const float* __restrict__ gk = g_proj[1];
    const float* __restrict__ gv = g_proj[2];
    const size_t headoff = (size_t)h * Ddim;

    // Load q tile (transposed) once
#pragma unroll
    for (int it = 0; it < 4; it++) {
        int idx = tid + it * 256;
        int r = idx >> 4;
        int dq = idx & 15;
        float4 v = *(const float4*)&gq[(size_t)(b * Ldim + r0 + r) * Edim + headoff + dq * 4];
        qt[(dq * 4 + 0) * AST + r] = v.x;
        qt[(dq * 4 + 1) * AST + r] = v.y;
        qt[(dq * 4 + 2) * AST + r] = v.z;
        qt[(dq * 4 + 3) * AST + r] = v.w;
    }
    if (tid < 64) csum[tid] = 0.f;
    __syncthreads();
    if (tid < 64) {
        float s0 = 0.f, s1 = 0.f, s2 = 0.f, s3 = 0.f;
#pragma unroll 4
        for (int d = 0; d < 64; d += 4) {
            float a0 = qt[(d + 0) * AST + tid];
            float a1 = qt[(d + 1) * AST + tid];
            float a2 = qt[(d + 2) * AST + tid];
            float a3 = qt[(d + 3) * AST + tid];
            s0 = fmaf(a0, a0, s0);
            s1 = fmaf(a1, a1, s1);
            s2 = fmaf(a2, a2, s2);
            s3 = fmaf(a3, a3, s3);
        }
        q2s[tid] = (s0 + s1) + (s2 + s3);
    }

    float m_r[4], Z_r[4], O[4][4];
#pragma unroll
    for (int i = 0; i < 4; i++) {
        m_r[i] = -1e30f;
        Z_r[i] = 0.f;
#pragma unroll
        for (int c = 0; c < 4; c++) O[i][c] = 0.f;
    }

    for (int j0 = 0; j0 < Ldim; j0 += 64) {
        __syncthreads();  // prior PV readers done (and q2s ready on first iter)

        // Load k tile (transposed) and v tile (row-major)
#pragma unroll
        for (int it = 0; it < 4; it++) {
            int idx = tid + it * 256;
            int r = idx >> 4;
            int dq = idx & 15;
            size_t base = (size_t)(b * Ldim + j0 + r) * Edim + headoff + dq * 4;
            float4 v = *(const float4*)&gk[base];
            kt[(dq * 4 + 0) * AST + r] = v.x;
            kt[(dq * 4 + 1) * AST + r] = v.y;
            kt[(dq * 4 + 2) * AST + r] = v.z;
            kt[(dq * 4 + 3) * AST + r] = v.w;
            float4 w = *(const float4*)&gv[base];
            *(float4*)&vs[r * 64 + dq * 4] = w;
        }
        __syncthreads();
        if (tid < 64) {
            float s0 = 0.f, s1 = 0.f, s2 = 0.f, s3 = 0.f;
#pragma unroll 4
            for (int d = 0; d < 64; d += 4) {
                float a0 = kt[(d + 0) * AST + tid];
                float a1 = kt[(d + 1) * AST + tid];
                float a2 = kt[(d + 2) * AST + tid];
                float a3 = kt[(d + 3) * AST + tid];
                s0 = fmaf(a0, a0, s0);
                s1 = fmaf(a1, a1, s1);
                s2 = fmaf(a2, a2, s2);
                s3 = fmaf(a3, a3, s3);
            }
            k2s[tid] = (s0 + s1) + (s2 + s3);
        }
        __syncthreads();

        // S = q . k  (4x4 per thread)
        float acc[4][4];
#pragma unroll
        for (int i = 0; i < 4; i++)
#pragma unroll
            for (int j = 0; j < 4; j++) acc[i][j] = 0.f;
#pragma unroll 8
        for (int d = 0; d < 64; d++) {
            float4 a = *(const float4*)&qt[d * AST + ty * 4];
            float4 bb = *(const float4*)&kt[d * AST + tx * 4];
            float av[4] = {a.x, a.y, a.z, a.w};
            float bv[4] = {bb.x, bb.y, bb.z, bb.w};
#pragma unroll
            for (int i = 0; i < 4; i++)
#pragma unroll
                for (int j = 0; j < 4; j++) acc[i][j] = fmaf(av[i], bv[j], acc[i][j]);
        }

        // scores + online softmax (rows are warp-local: 16 lanes per row group)
        float p[4][4];
#pragma unroll
        for (int i = 0; i < 4; i++) {
            float q2 = q2s[ty * 4 + i];
            float srow[4];
            float mx = -1e30f;
#pragma unroll
            for (int j = 0; j < 4; j++) {
                float d2 = fmaxf(q2 + k2s[tx * 4 + j] - 2.f * acc[i][j], 0.f);
                float s = -__fsqrt_rn(d2);
                srow[j] = s;
                mx = fmaxf(mx, s);
            }
            mx = fmaxf(mx, __shfl_xor_sync(0xffffffffu, mx, 8));
            mx = fmaxf(mx, __shfl_xor_sync(0xffffffffu, mx, 4));
            mx = fmaxf(mx, __shfl_xor_sync(0xffffffffu, mx, 2));
            mx = fmaxf(mx, __shfl_xor_sync(0xffffffffu, mx, 1));
            float mnew = fmaxf(m_r[i], mx);
            float scale = __expf(m_r[i] - mnew);
            float rs = 0.f;
#pragma unroll
            for (int j = 0; j < 4; j++) {
                p[i][j] = __expf(srow[j] - mnew);
                rs += p[i][j];
            }
            rs += __shfl_xor_sync(0xffffffffu, rs, 8);
            rs += __shfl_xor_sync(0xffffffffu, rs, 4);
            rs += __shfl_xor_sync(0xffffffffu, rs, 2);
            rs += __shfl_xor_sync(0xffffffffu, rs, 1);
            Z_r[i] = Z_r[i] * scale + rs;
            m_r[i] = mnew;
#pragma unroll
            for (int c = 0; c < 4; c++) O[i][c] *= scale;
        }

        __syncthreads();  // everyone done reading kt
        // store P transposed into the kt buffer: Pt[j][r]
#pragma unroll
        for (int j = 0; j < 4; j++)
#pragma unroll
            for (int i = 0; i < 4; i++)
                kt[(tx * 4 + j) * AST + ty * 4 + i] = p[i][j];
        __syncthreads();

        // O += P @ V
#pragma unroll 8
        for (int j = 0; j < 64; j++) {
            float4 pv = *(const float4*)&kt[j * AST + ty * 4];
            float4 vv = *(const float4*)&vs[j * 64 + tx * 4];
            float pa[4] = {pv.x, pv.y, pv.z, pv.w};
            float va[4] = {vv.x, vv.y, vv.z, vv.w};
#pragma unroll
            for (int i = 0; i < 4; i++)
#pragma unroll
                for (int c = 0; c < 4; c++) O[i][c] = fmaf(pa[i], va[c], O[i][c]);
        }
    }

    // normalize rows by Z, reduce over the 64 query rows (sum), accumulate
    float cp[4];
#pragma unroll
    for (int c = 0; c < 4; c++) cp[c] = 0.f;
#pragma unroll
    for (int i = 0; i < 4; i++) {
        float inv = 1.f / Z_r[i];
#pragma unroll
        for (int c = 0; c < 4; c++) cp[c] = fmaf(O[i][c], inv, cp[c]);
    }
#pragma unroll
    for (int c = 0; c < 4; c++) atomicAdd(&csum[tx * 4 + c], cp[c]);
    __syncthreads();
    if (tid < 64) atomicAdd(&g_ho[(size_t)b * Edim + headoff + tid], csum[tid]);
}

// ======================================================================
// Final: out[b, e'] = sum_e ho[b, e] * Wo[e', e]   (warp per output)
// ======================================================================
__global__ void __launch_bounds__(256) out_kernel(const float* __restrict__ Wo,
                                                  float* __restrict__ out)
{
    int gw = (blockIdx.x * blockDim.x + threadIdx.x) >> 5;
    int lane = threadIdx.x & 31;
    int b = gw >> 10;
    int ep = gw & 1023;
    const float* ho = &g_ho[(size_t)b * Edim];
    const float* wr = &Wo[(size_t)ep * Edim];
    float s = 0.f;
    for (int e = lane * 4; e < Edim; e += 128) {
        float4 w4 = *(const float4*)&wr[e];
        float4 h4 = *(const float4*)&ho[e];
        s = fmaf(w4.x, h4.x, s);
        s = fmaf(w4.y, h4.y, s);
        s = fmaf(w4.z, h4.z, s);
        s = fmaf(w4.w, h4.w, s);
    }
#pragma unroll
    for (int off = 16; off; off >>= 1) s += __shfl_xor_sync(0xffffffffu, s, off);
    if (lane == 0) out[(size_t)b * Edim + ep] = s;
}

// ======================================================================
extern "C" void kernel_launch(void* const* d_in, const int* in_sizes, int n_in,
                              void* d_out, int out_size)
{
    const float* Q = (const float*)d_in[0];
    const float* K = (const float*)d_in[1];
    const float* V = (const float*)d_in[2];
    const float* Wq = (const float*)d_in[3];
    const float* Wk = (const float*)d_in[4];
    const float* Wv = (const float*)d_in[5];
    const float* Wo = (const float*)d_in[6];
    float* out = (float*)d_out;

    cudaFuncSetAttribute(attn_kernel, cudaFuncAttributeMaxDynamicSharedMemorySize, ASM_BYTES);

    proj_kernel<<<dim3(NROWS / 128, Edim / 128, 3), 256>>>(Q, K, V, Wq, Wk, Wv);
    zero_ho_kernel<<<2, 1024>>>();
    attn_kernel<<<dim3(Ldim / 64, Bdim * Hdim), 256, ASM_BYTES>>>();
    out_kernel<<<256, 256>>>(Wo, out);
}

// round 3
// speedup vs baseline: 1.4258x; 1.4258x over previous
#include <cuda_runtime.h>
#include <math.h>
#include <cstdint>

#define Bdim 2
#define Ldim 2048
#define Edim 1024
#define Hdim 16
#define Ddim 64
#define NROWS (Bdim * Ldim)  // 4096

// Scratch (allocation-free rule: __device__ globals)
__device__ float g_proj[3][(size_t)NROWS * Edim];  // q, k, v projections, (B*L, E) row-major
__device__ float g_ho[Bdim * Edim];                // per-(b,h,d) accumulated head output

// ======================================================================
// Portable helpers (plain sm_103 target: NO tcgen05, mma.sync only)
// ======================================================================
__device__ __forceinline__ uint32_t smem_to_u32(const void* smem_ptr) {
    uint32_t addr;
    asm("{ .reg .u64 tmp; cvta.to.shared.u64 tmp, %1; cvt.u32.u64 %0, tmp; }"
        : "=r"(addr) : "l"(smem_ptr));
    return addr;
}
__device__ __forceinline__ void cp_async16(uint32_t s, const void* g) {
    asm volatile("cp.async.cg.shared.global [%0], [%1], 16;" :: "r"(s), "l"(g) : "memory");
}
__device__ __forceinline__ void cp_commit() {
    asm volatile("cp.async.commit_group;" ::: "memory");
}
template <int N>
__device__ __forceinline__ void cp_wait() {
    asm volatile("cp.async.wait_group %0;" :: "n"(N) : "memory");
}

// m16n8k8 tf32 mma: D = A*B + D (fp32 accum). A row-major 16x8, B col-major 8x8.
__device__ __forceinline__ void mma_tf32(float c[4], const uint32_t a[4], const uint32_t b[2]) {
    asm volatile(
        "mma.sync.aligned.m16n8k8.row.col.f32.tf32.tf32.f32 "
        "{%0,%1,%2,%3}, {%4,%5,%6,%7}, {%8,%9}, {%0,%1,%2,%3};"
        : "+f"(c[0]), "+f"(c[1]), "+f"(c[2]), "+f"(c[3])
        : "r"(a[0]), "r"(a[1]), "r"(a[2]), "r"(a[3]), "r"(b[0]), "r"(b[1]));
}

// ======================================================================
// Projection GEMM on tensor cores (mma.sync tf32):  C = X @ W^T
// CTA tile 128x128, K-chunks of 32, double-buffered SMEM via cp.async.
// 8 warps in 2(m) x 4(n) grid; warp tile 64x32 = 4x4 m16n8 fragments.
// SMEM row stride = 36 floats: fragment LDS is bank-conflict-free
// (bank = 4*row + col over rows 0..7, cols 0..3 -> all distinct).
// ======================================================================
#define PJST 36
#define PJ_TILE_FLOATS (128 * PJST)                 // one 128x32 tile (padded)
#define PJ_BUF_FLOATS (2 * PJ_TILE_FLOATS)          // A tile + B tile
#define PJ_SMEM_BYTES (2 * PJ_BUF_FLOATS * 4)       // double buffered = 73728

__global__ void __launch_bounds__(256) proj_mma_kernel(
    const float* __restrict__ Q, const float* __restrict__ K, const float* __restrict__ V,
    const float* __restrict__ Wq, const float* __restrict__ Wk, const float* __restrict__ Wv)
{
    extern __shared__ float smem[];
    const uint32_t smem_u32 = smem_to_u32(smem);

    const int z = blockIdx.z;
    const float* __restrict__ X = (z == 0) ? Q : ((z == 1) ? K : V);
    const float* __restrict__ W = (z == 0) ? Wq : ((z == 1) ? Wk : Wv);
    float* __restrict__ C = g_proj[z];
    const int m0 = blockIdx.x * 128;
    const int n0 = blockIdx.y * 128;

    const int tid = threadIdx.x;
    const int wid = tid >> 5;
    const int lane = tid & 31;
    const int g = lane >> 2;   // group id (row within fragment)
    const int t = lane & 3;    // thread-in-group (col within fragment)
    const int wm = (wid >> 2) * 64;  // warp m offset in CTA tile
    const int wn = (wid & 3) * 32;   // warp n offset

    // per-thread load slots: 4 float4 for A, 4 for B per chunk
    const int lrow = tid >> 1;          // unused pattern; use idx mapping below
    (void)lrow;

    float c[4][4][4];
#pragma unroll
    for (int mi = 0; mi < 4; mi++)
#pragma unroll
        for (int ni = 0; ni < 4; ni++)
#pragma unroll
            for (int r = 0; r < 4; r++) c[mi][ni][r] = 0.f;

    // ---- async load of chunk `cc` into buffer cc&1 ----
    auto load_chunk = [&](int cc) {
        const int k0 = cc * 32;
        float* buf = smem + (cc & 1) * PJ_BUF_FLOATS;
        uint32_t abase = smem_u32 + (uint32_t)((cc & 1) * PJ_BUF_FLOATS) * 4u;
#pragma unroll
        for (int it = 0; it < 4; it++) {
            int idx = tid + it * 256;   // 0..1023
            int row = idx >> 3;         // 0..127
            int q = idx & 7;            // 16B quad
            uint32_t soff = (uint32_t)(row * PJST + q * 4) * 4u;
            cp_async16(abase + soff, &X[(size_t)(m0 + row) * Edim + k0 + q * 4]);
            cp_async16(abase + (uint32_t)PJ_TILE_FLOATS * 4u + soff,
                       &W[(size_t)(n0 + row) * Edim + k0 + q * 4]);
        }
        (void)buf;
        cp_commit();
    };

    load_chunk(0);

    for (int cc = 0; cc < 32; cc++) {
        if (cc + 1 < 32) {
            load_chunk(cc + 1);
            cp_wait<1>();
        } else {
            cp_wait<0>();
        }
        __syncthreads();

        const float* As_ = smem + (cc & 1) * PJ_BUF_FLOATS;
        const float* Bs_ = As_ + PJ_TILE_FLOATS;

#pragma unroll
        for (int ks = 0; ks < 4; ks++) {
            const int k0 = ks * 8;
            uint32_t a[4][4], bf[4][2];
#pragma unroll
            for (int mi = 0; mi < 4; mi++) {
                const float* ap = As_ + (wm + mi * 16 + g) * PJST + k0 + t;
                a[mi][0] = __float_as_uint(ap[0]);
                a[mi][1] = __float_as_uint(ap[8 * PJST]);
                a[mi][2] = __float_as_uint(ap[4]);
                a[mi][3] = __float_as_uint(ap[8 * PJST + 4]);
            }
#pragma unroll
            for (int ni = 0; ni < 4; ni++) {
                const float* bp = Bs_ + (wn + ni * 8 + g) * PJST + k0 + t;
                bf[ni][0] = __float_as_uint(bp[0]);
                bf[ni][1] = __float_as_uint(bp[4]);
            }
#pragma unroll
            for (int mi = 0; mi < 4; mi++)
#pragma unroll
                for (int ni = 0; ni < 4; ni++) mma_tf32(c[mi][ni], a[mi], bf[ni]);
        }
        __syncthreads();  // all warps done reading buffer (cc&1) before it is reloaded
    }

    // epilogue: c[mi][ni] rows {g, g+8}, cols {2t, 2t+1} within the m16n8 tile
#pragma unroll
    for (int mi = 0; mi < 4; mi++) {
        int row = m0 + wm + mi * 16 + g;
#pragma unroll
        for (int ni = 0; ni < 4; ni++) {
            int col = n0 + wn + ni * 8 + 2 * t;
            *(float2*)&C[(size_t)row * Edim + col] = make_float2(c[mi][ni][0], c[mi][ni][1]);
            *(float2*)&C[(size_t)(row + 8) * Edim + col] = make_float2(c[mi][ni][2], c[mi][ni][3]);
        }
    }
}

// ======================================================================
// Zero the head-output accumulator
// ======================================================================
__global__ void zero_ho_kernel()
{
    int i = blockIdx.x * blockDim.x + threadIdx.x;
    if (i < Bdim * Edim) g_ho[i] = 0.f;
}

// ======================================================================
// Flash-style L2-distance attention (SIMT, unchanged from R1 — passed)
// ======================================================================
#define AST 76
#define ASM_FLOATS (64 * AST * 2 + 64 * 64 + 192)
#define ASM_BYTES (ASM_FLOATS * 4)

__global__ void __launch_bounds__(256) attn_kernel()
{
    extern __shared__ float sm[];
    float* qt = sm;
    float* kt = qt + 64 * AST;
    float* vs = kt + 64 * AST;
    float* q2s = vs + 64 * 64;
    float* k2s = q2s + 64;
    float* csum = k2s + 64;

    const int tid = threadIdx.x;
    const int tx = tid & 15;
    const int ty = tid >> 4;
    const int bh = blockIdx.y;
    const int b = bh >> 4;
    const int h = bh & 15;
    const int r0 = blockIdx.x * 64;

    const float* __restrict__ gq = g_proj[0];
    const float* __restrict__ gk = g_proj[1];
    const float* __restrict__ gv = g_proj[2];
    const size_t headoff = (size_t)h * Ddim;

#pragma unroll
    for (int it = 0; it < 4; it++) {
        int idx = tid + it * 256;
        int r = idx >> 4;
        int dq = idx & 15;
        float4 v = *(const float4*)&gq[(size_t)(b * Ldim + r0 + r) * Edim + headoff + dq * 4];
        qt[(dq * 4 + 0) * AST + r] = v.x;
        qt[(dq * 4 + 1) * AST + r] = v.y;
        qt[(dq * 4 + 2) * AST + r] = v.z;
        qt[(dq * 4 + 3) * AST + r] = v.w;
    }
    if (tid < 64) csum[tid] = 0.f;
    __syncthreads();
    if (tid < 64) {
        float s0 = 0.f, s1 = 0.f, s2 = 0.f, s3 = 0.f;
#pragma unroll 4
        for (int d = 0; d < 64; d += 4) {
            float a0 = qt[(d + 0) * AST + tid];
            float a1 = qt[(d + 1) * AST + tid];
            float a2 = qt[(d + 2) * AST + tid];
            float a3 = qt[(d + 3) * AST + tid];
            s0 = fmaf(a0, a0, s0);
            s1 = fmaf(a1, a1, s1);
            s2 = fmaf(a2, a2, s2);
            s3 = fmaf(a3, a3, s3);
        }
        q2s[tid] = (s0 + s1) + (s2 + s3);
    }

    float m_r[4], Z_r[4], O[4][4];
#pragma unroll
    for (int i = 0; i < 4; i++) {
        m_r[i] = -1e30f;
        Z_r[i] = 0.f;
#pragma unroll
        for (int c = 0; c < 4; c++) O[i][c] = 0.f;
    }

    for (int j0 = 0; j0 < Ldim; j0 += 64) {
        __syncthreads();

#pragma unroll
        for (int it = 0; it < 4; it++) {
            int idx = tid + it * 256;
            int r = idx >> 4;
            int dq = idx & 15;
            size_t base = (size_t)(b * Ldim + j0 + r) * Edim + headoff + dq * 4;
            float4 v = *(const float4*)&gk[base];
            kt[(dq * 4 + 0) * AST + r] = v.x;
            kt[(dq * 4 + 1) * AST + r] = v.y;
            kt[(dq * 4 + 2) * AST + r] = v.z;
            kt[(dq * 4 + 3) * AST + r] = v.w;
            float4 w = *(const float4*)&gv[base];
            *(float4*)&vs[r * 64 + dq * 4] = w;
        }
        __syncthreads();
        if (tid < 64) {
            float s0 = 0.f, s1 = 0.f, s2 = 0.f, s3 = 0.f;
#pragma unroll 4
            for (int d = 0; d < 64; d += 4) {
                float a0 = kt[(d + 0) * AST + tid];
                float a1 = kt[(d + 1) * AST + tid];
                float a2 = kt[(d + 2) * AST + tid];
                float a3 = kt[(d + 3) * AST + tid];
                s0 = fmaf(a0, a0, s0);
                s1 = fmaf(a1, a1, s1);
                s2 = fmaf(a2, a2, s2);
                s3 = fmaf(a3, a3, s3);
            }
            k2s[tid] = (s0 + s1) + (s2 + s3);
        }
        __syncthreads();

        float acc[4][4];
#pragma unroll
        for (int i = 0; i < 4; i++)
#pragma unroll
            for (int j = 0; j < 4; j++) acc[i][j] = 0.f;
#pragma unroll 8
        for (int d = 0; d < 64; d++) {
            float4 a = *(const float4*)&qt[d * AST + ty * 4];
            float4 bb = *(const float4*)&kt[d * AST + tx * 4];
            float av[4] = {a.x, a.y, a.z, a.w};
            float bv[4] = {bb.x, bb.y, bb.z, bb.w};
#pragma unroll
            for (int i = 0; i < 4; i++)
#pragma unroll
                for (int j = 0; j < 4; j++) acc[i][j] = fmaf(av[i], bv[j], acc[i][j]);
        }

        float p[4][4];
#pragma unroll
        for (int i = 0; i < 4; i++) {
            float q2 = q2s[ty * 4 + i];
            float srow[4];
            float mx = -1e30f;
#pragma unroll
            for (int j = 0; j < 4; j++) {
                float d2 = fmaxf(q2 + k2s[tx * 4 + j] - 2.f * acc[i][j], 0.f);
                float s = -__fsqrt_rn(d2);
                srow[j] = s;
                mx = fmaxf(mx, s);
            }
            mx = fmaxf(mx, __shfl_xor_sync(0xffffffffu, mx, 8));
            mx = fmaxf(mx, __shfl_xor_sync(0xffffffffu, mx, 4));
            mx = fmaxf(mx, __shfl_xor_sync(0xffffffffu, mx, 2));
            mx = fmaxf(mx, __shfl_xor_sync(0xffffffffu, mx, 1));
            float mnew = fmaxf(m_r[i], mx);
            float scale = __expf(m_r[i] - mnew);
            float rs = 0.f;
#pragma unroll
            for (int j = 0; j < 4; j++) {
                p[i][j] = __expf(srow[j] - mnew);
                rs += p[i][j];
            }
            rs += __shfl_xor_sync(0xffffffffu, rs, 8);
            rs += __shfl_xor_sync(0xffffffffu, rs, 4);
            rs += __shfl_xor_sync(0xffffffffu, rs, 2);
            rs += __shfl_xor_sync(0xffffffffu, rs, 1);
            Z_r[i] = Z_r[i] * scale + rs;
            m_r[i] = mnew;
#pragma unroll
            for (int c = 0; c < 4; c++) O[i][c] *= scale;
        }

        __syncthreads();
#pragma unroll
        for (int j = 0; j < 4; j++)
#pragma unroll
            for (int i = 0; i < 4; i++)
                kt[(tx * 4 + j) * AST + ty * 4 + i] = p[i][j];
        __syncthreads();

#pragma unroll 8
        for (int j = 0; j < 64; j++) {
            float4 pv = *(const float4*)&kt[j * AST + ty * 4];
            float4 vv = *(const float4*)&vs[j * 64 + tx * 4];
            float pa[4] = {pv.x, pv.y, pv.z, pv.w};
            float va[4] = {vv.x, vv.y, vv.z, vv.w};
#pragma unroll
            for (int i = 0; i < 4; i++)
#pragma unroll
                for (int c = 0; c < 4; c++) O[i][c] = fmaf(pa[i], va[c], O[i][c]);
        }
    }

    float cp[4];
#pragma unroll
    for (int c = 0; c < 4; c++) cp[c] = 0.f;
#pragma unroll
    for (int i = 0; i < 4; i++) {
        float inv = 1.f / Z_r[i];
#pragma unroll
        for (int c = 0; c < 4; c++) cp[c] = fmaf(O[i][c], inv, cp[c]);
    }
#pragma unroll
    for (int c = 0; c < 4; c++) atomicAdd(&csum[tx * 4 + c], cp[c]);
    __syncthreads();
    if (tid < 64) atomicAdd(&g_ho[(size_t)b * Edim + headoff + tid], csum[tid]);
}

// ======================================================================
// Final: out[b, e'] = sum_e ho[b, e] * Wo[e', e]   (warp per output)
// ======================================================================
__global__ void __launch_bounds__(256) out_kernel(const float* __restrict__ Wo,
                                                  float* __restrict__ out)
{
    int gw = (blockIdx.x * blockDim.x + threadIdx.x) >> 5;
    int lane = threadIdx.x & 31;
    int b = gw >> 10;
    int ep = gw & 1023;
    const float* ho = &g_ho[(size_t)b * Edim];
    const float* wr = &Wo[(size_t)ep * Edim];
    float s = 0.f;
    for (int e = lane * 4; e < Edim; e += 128) {
        float4 w4 = *(const float4*)&wr[e];
        float4 h4 = *(const float4*)&ho[e];
        s = fmaf(w4.x, h4.x, s);
        s = fmaf(w4.y, h4.y, s);
        s = fmaf(w4.z, h4.z, s);
        s = fmaf(w4.w, h4.w, s);
    }
#pragma unroll
    for (int off = 16; off; off >>= 1) s += __shfl_xor_sync(0xffffffffu, s, off);
    if (lane == 0) out[(size_t)b * Edim + ep] = s;
}

// ======================================================================
extern "C" void kernel_launch(void* const* d_in, const int* in_sizes, int n_in,
                              void* d_out, int out_size)
{
    const float* Q = (const float*)d_in[0];
    const float* K = (const float*)d_in[1];
    const float* V = (const float*)d_in[2];
    const float* Wq = (const float*)d_in[3];
    const float* Wk = (const float*)d_in[4];
    const float* Wv = (const float*)d_in[5];
    const float* Wo = (const float*)d_in[6];
    float* out = (float*)d_out;

    cudaFuncSetAttribute(proj_mma_kernel, cudaFuncAttributeMaxDynamicSharedMemorySize, PJ_SMEM_BYTES);
    cudaFuncSetAttribute(attn_kernel, cudaFuncAttributeMaxDynamicSharedMemorySize, ASM_BYTES);

    proj_mma_kernel<<<dim3(NROWS / 128, Edim / 128, 3), 256, PJ_SMEM_BYTES>>>(Q, K, V, Wq, Wk, Wv);
    zero_ho_kernel<<<2, 1024>>>();
    attn_kernel<<<dim3(Ldim / 64, Bdim * Hdim), 256, ASM_BYTES>>>();
    out_kernel<<<256, 256>>>(Wo, out);
}

// round 4
// speedup vs baseline: 3.3737x; 2.3662x over previous
#include <cuda_runtime.h>
#include <cuda_bf16.h>
#include <math.h>
#include <cstdint>

#define Bdim 2
#define Ldim 2048
#define Edim 1024
#define Hdim 16
#define Ddim 64
#define NROWS (Bdim * Ldim)  // 4096
#define NBH (Bdim * Hdim)    // 32

// Scratch (allocation-free rule: __device__ globals)
__device__ float g_proj[3][(size_t)NROWS * Edim];     // q,k,v projections
__device__ float g_q2[NBH * Ldim];                    // ||q||^2 per (bh, l)
__device__ float g_k2[NBH * Ldim];                    // ||k||^2 per (bh, l)
__device__ float g_invZ[NBH * Ldim];                  // 1/Z per (bh, q)
__device__ float g_w[NBH * Ldim];                     // attention column sums
__device__ float g_ho[Bdim * Edim];                   // head outputs (summed over q)
__device__ unsigned short g_e[(size_t)NBH * Ldim * Ldim];  // exp scores, bf16 (268MB)

// ======================================================================
// Helpers (plain sm_103 target: mma.sync + cp.async only)
// ======================================================================
__device__ __forceinline__ uint32_t smem_to_u32(const void* smem_ptr) {
    uint32_t addr;
    asm("{ .reg .u64 tmp; cvta.to.shared.u64 tmp, %1; cvt.u32.u64 %0, tmp; }"
        : "=r"(addr) : "l"(smem_ptr));
    return addr;
}
__device__ __forceinline__ void cp_async16(uint32_t s, const void* g) {
    asm volatile("cp.async.cg.shared.global [%0], [%1], 16;" :: "r"(s), "l"(g) : "memory");
}
__device__ __forceinline__ void cp_commit() {
    asm volatile("cp.async.commit_group;" ::: "memory");
}
template <int N>
__device__ __forceinline__ void cp_wait() {
    asm volatile("cp.async.wait_group %0;" :: "n"(N) : "memory");
}
// round-to-nearest fp32 -> tf32 (halves HMMA truncation error, removes bias)
__device__ __forceinline__ uint32_t f2tf(float x) {
    uint32_t r;
    asm("cvt.rna.tf32.f32 %0, %1;" : "=r"(r) : "f"(x));
    return r;
}
__device__ __forceinline__ float fast_sqrt(float x) {
    float r; asm("sqrt.approx.f32 %0, %1;" : "=f"(r) : "f"(x)); return r;
}
__device__ __forceinline__ float fast_ex2(float x) {
    float r; asm("ex2.approx.f32 %0, %1;" : "=f"(r) : "f"(x)); return r;
}
__device__ __forceinline__ void mma_tf32(float c[4], const uint32_t a[4], const uint32_t b[2]) {
    asm volatile(
        "mma.sync.aligned.m16n8k8.row.col.f32.tf32.tf32.f32 "
        "{%0,%1,%2,%3}, {%4,%5,%6,%7}, {%8,%9}, {%0,%1,%2,%3};"
        : "+f"(c[0]), "+f"(c[1]), "+f"(c[2]), "+f"(c[3])
        : "r"(a[0]), "r"(a[1]), "r"(a[2]), "r"(a[3]), "r"(b[0]), "r"(b[1]));
}

// ======================================================================
// Projection GEMM (mma.sync tf32, rna-rounded):  C = X @ W^T
// ======================================================================
#define PJST 36
#define PJ_TILE_FLOATS (128 * PJST)
#define PJ_BUF_FLOATS (2 * PJ_TILE_FLOATS)
#define PJ_SMEM_BYTES (2 * PJ_BUF_FLOATS * 4)

__global__ void __launch_bounds__(256) proj_mma_kernel(
    const float* __restrict__ Q, const float* __restrict__ K, const float* __restrict__ V,
    const float* __restrict__ Wq, const float* __restrict__ Wk, const float* __restrict__ Wv)
{
    extern __shared__ float smem[];
    const uint32_t smem_u32 = smem_to_u32(smem);

    const int z = blockIdx.z;
    const float* __restrict__ X = (z == 0) ? Q : ((z == 1) ? K : V);
    const float* __restrict__ W = (z == 0) ? Wq : ((z == 1) ? Wk : Wv);
    float* __restrict__ C = g_proj[z];
    const int m0 = blockIdx.x * 128;
    const int n0 = blockIdx.y * 128;

    const int tid = threadIdx.x;
    const int wid = tid >> 5;
    const int lane = tid & 31;
    const int g = lane >> 2;
    const int t = lane & 3;
    const int wm = (wid >> 2) * 64;
    const int wn = (wid & 3) * 32;

    float c[4][4][4];
#pragma unroll
    for (int mi = 0; mi < 4; mi++)
#pragma unroll
        for (int ni = 0; ni < 4; ni++)
#pragma unroll
            for (int r = 0; r < 4; r++) c[mi][ni][r] = 0.f;

    auto load_chunk = [&](int cc) {
        const int k0 = cc * 32;
        uint32_t abase = smem_u32 + (uint32_t)((cc & 1) * PJ_BUF_FLOATS) * 4u;
#pragma unroll
        for (int it = 0; it < 4; it++) {
            int idx = tid + it * 256;
            int row = idx >> 3;
            int q = idx & 7;
            uint32_t soff = (uint32_t)(row * PJST + q * 4) * 4u;
            cp_async16(abase + soff, &X[(size_t)(m0 + row) * Edim + k0 + q * 4]);
            cp_async16(abase + (uint32_t)PJ_TILE_FLOATS * 4u + soff,
                       &W[(size_t)(n0 + row) * Edim + k0 + q * 4]);
        }
        cp_commit();
    };

    load_chunk(0);

    for (int cc = 0; cc < 32; cc++) {
        if (cc + 1 < 32) {
            load_chunk(cc + 1);
            cp_wait<1>();
        } else {
            cp_wait<0>();
        }
        __syncthreads();

        const float* As_ = smem + (cc & 1) * PJ_BUF_FLOATS;
        const float* Bs_ = As_ + PJ_TILE_FLOATS;

#pragma unroll
        for (int ks = 0; ks < 4; ks++) {
            const int k0 = ks * 8;
            uint32_t a[4][4], bf[4][2];
#pragma unroll
            for (int mi = 0; mi < 4; mi++) {
                const float* ap = As_ + (wm + mi * 16 + g) * PJST + k0 + t;
                a[mi][0] = f2tf(ap[0]);
                a[mi][1] = f2tf(ap[8 * PJST]);
                a[mi][2] = f2tf(ap[4]);
                a[mi][3] = f2tf(ap[8 * PJST + 4]);
            }
#pragma unroll
            for (int ni = 0; ni < 4; ni++) {
                const float* bp = Bs_ + (wn + ni * 8 + g) * PJST + k0 + t;
                bf[ni][0] = f2tf(bp[0]);
                bf[ni][1] = f2tf(bp[4]);
            }
#pragma unroll
            for (int mi = 0; mi < 4; mi++)
#pragma unroll
                for (int ni = 0; ni < 4; ni++) mma_tf32(c[mi][ni], a[mi], bf[ni]);
        }
        __syncthreads();
    }

#pragma unroll
    for (int mi = 0; mi < 4; mi++) {
        int row = m0 + wm + mi * 16 + g;
#pragma unroll
        for (int ni = 0; ni < 4; ni++) {
            int col = n0 + wn + ni * 8 + 2 * t;
            *(float2*)&C[(size_t)row * Edim + col] = make_float2(c[mi][ni][0], c[mi][ni][1]);
            *(float2*)&C[(size_t)(row + 8) * Edim + col] = make_float2(c[mi][ni][2], c[mi][ni][3]);
        }
    }
}

// ======================================================================
// Precompute ||q||^2 and ||k||^2 per (bh, l). One warp per row.
// ======================================================================
__global__ void __launch_bounds__(256) prep_sq_kernel()
{
    const int gwid = blockIdx.x * 8 + (threadIdx.x >> 5);
    const int lane = threadIdx.x & 31;
    const int arr = gwid >> 16;          // 0 = q, 1 = k
    const int rem = gwid & 65535;
    const int bh = rem >> 11;
    const int l = rem & 2047;
    const int b = bh >> 4;
    const int h = bh & 15;
    const float* src = g_proj[arr] + (size_t)(b * Ldim + l) * Edim + h * Ddim;
    float2 v = ((const float2*)src)[lane];
    float s = v.x * v.x + v.y * v.y;
#pragma unroll
    for (int off = 16; off; off >>= 1) s += __shfl_xor_sync(0xffffffffu, s, off);
    if (lane == 0) (arr ? g_k2 : g_q2)[bh * Ldim + l] = s;
}

// ======================================================================
// Attention pass A: per (q-block 128, bh): S = QK^T on tensor cores,
// e = exp(-sqrt(max(q2+k2-2qk,0))) with m=0 (scores always <= 0),
// stream e (bf16) to g_e, accumulate row sums Z -> g_invZ.
// ======================================================================
#define AQST 68
#define A_SM_Q (128 * AQST)
#define A_SM_K (128 * AQST)
#define A_SMEM_FLOATS (A_SM_Q + 2 * A_SM_K + 128)
#define A_SMEM_BYTES (A_SMEM_FLOATS * 4)

__global__ void __launch_bounds__(256, 2) attn_passA_kernel()
{
    extern __shared__ float sm[];
    float* qs = sm;
    float* ks_ = sm + A_SM_Q;
    float* zsh = sm + A_SM_Q + 2 * A_SM_K;
    const uint32_t qs_u = smem_to_u32(qs);
    const uint32_t ks_u = smem_to_u32(ks_);

    const int tid = threadIdx.x;
    const int wid = tid >> 5;
    const int lane = tid & 31;
    const int g = lane >> 2;
    const int t = lane & 3;
    const int wm = (wid >> 2) * 64;
    const int wn = (wid & 3) * 32;
    const int bh = blockIdx.y;
    const int b = bh >> 4;
    const int h = bh & 15;
    const int qbase = blockIdx.x * 128;

    if (tid < 128) zsh[tid] = 0.f;

    const float* gq = g_proj[0] + (size_t)(b * Ldim + qbase) * Edim + h * Ddim;
    const float* gk = g_proj[1] + (size_t)(b * Ldim) * Edim + h * Ddim;

    // Q tile (cp.async group 0)
#pragma unroll
    for (int it = 0; it < 8; it++) {
        int idx = tid + it * 256;
        int r = idx >> 4;
        int qd = idx & 15;
        cp_async16(qs_u + (uint32_t)(r * AQST + qd * 4) * 4u, gq + (size_t)r * Edim + qd * 4);
    }
    cp_commit();

    auto load_k = [&](int jt) {
        uint32_t base = ks_u + (uint32_t)((jt & 1) * A_SM_K) * 4u;
#pragma unroll
        for (int it = 0; it < 8; it++) {
            int idx = tid + it * 256;
            int r = idx >> 4;
            int qd = idx & 15;
            cp_async16(base + (uint32_t)(r * AQST + qd * 4) * 4u,
                       gk + (size_t)(jt * 128 + r) * Edim + qd * 4);
        }
        cp_commit();
    };

    load_k(0);

    // wait for Q (group 0); K0 may still be pending
    cp_wait<1>();
    __syncthreads();
    // pre-round Q tile to tf32 (rna) in place: fragment loads skip cvt
    for (int i = tid; i < 128 * 64; i += 256) {
        int r = i >> 6;
        int cc = i & 63;
        float* p = &qs[r * AQST + cc];
        *p = __uint_as_float(f2tf(*p));
    }

    // per-thread row constants
    float q2r[8];
    const float* q2p = g_q2 + bh * Ldim + qbase;
#pragma unroll
    for (int i = 0; i < 8; i++) q2r[i] = q2p[wm + (i >> 1) * 16 + (i & 1) * 8 + g];

    // base pointer into g_e for this thread's row g (other rows via imm offsets)
    unsigned short* pe0 = g_e + ((size_t)bh * Ldim + qbase + wm + g) * Ldim + wn + 2 * t;

    float zloc[8];
#pragma unroll
    for (int i = 0; i < 8; i++) zloc[i] = 0.f;

    for (int jt = 0; jt < 16; jt++) {
        if (jt + 1 < 16) {
            load_k(jt + 1);
            cp_wait<1>();
        } else {
            cp_wait<0>();
        }
        __syncthreads();

        const float* kb = ks_ + (jt & 1) * A_SM_K;

        float c[4][4][4];
#pragma unroll
        for (int mi = 0; mi < 4; mi++)
#pragma unroll
            for (int ni = 0; ni < 4; ni++)
#pragma unroll
                for (int r = 0; r < 4; r++) c[mi][ni][r] = 0.f;

#pragma unroll
        for (int ksb = 0; ksb < 8; ksb++) {
            const int k0 = ksb * 8;
            uint32_t a[4][4], bf[4][2];
#pragma unroll
            for (int mi = 0; mi < 4; mi++) {
                const float* ap = qs + (wm + mi * 16 + g) * AQST + k0 + t;
                a[mi][0] = __float_as_uint(ap[0]);
                a[mi][1] = __float_as_uint(ap[8 * AQST]);
                a[mi][2] = __float_as_uint(ap[4]);
                a[mi][3] = __float_as_uint(ap[8 * AQST + 4]);
            }
#pragma unroll
            for (int ni = 0; ni < 4; ni++) {
                const float* bp = kb + (wn + ni * 8 + g) * AQST + k0 + t;
                bf[ni][0] = f2tf(bp[0]);
                bf[ni][1] = f2tf(bp[4]);
            }
#pragma unroll
            for (int mi = 0; mi < 4; mi++)
#pragma unroll
                for (int ni = 0; ni < 4; ni++) mma_tf32(c[mi][ni], a[mi], bf[ni]);
        }

        // epilogue: scores -> e (bf16 store) + Z accumulation
        const float* k2p = g_k2 + bh * Ldim + jt * 128;
        unsigned short* pet = pe0 + jt * 128;
#pragma unroll
        for (int ni = 0; ni < 4; ni++) {
            float2 k2c = *(const float2*)&k2p[wn + ni * 8 + 2 * t];
#pragma unroll
            for (int mi = 0; mi < 4; mi++) {
#pragma unroll
                for (int half = 0; half < 2; half++) {
                    float s0 = fmaf(-2.f, c[mi][ni][half * 2 + 0], q2r[mi * 2 + half] + k2c.x);
                    float s1 = fmaf(-2.f, c[mi][ni][half * 2 + 1], q2r[mi * 2 + half] + k2c.y);
                    float e0 = fast_ex2(fast_sqrt(fmaxf(s0, 0.f)) * -1.44269504f);
                    float e1 = fast_ex2(fast_sqrt(fmaxf(s1, 0.f)) * -1.44269504f);
                    zloc[mi * 2 + half] += e0 + e1;
                    __nv_bfloat162 bb = __float22bfloat162_rn(make_float2(e0, e1));
                    *(__nv_bfloat162*)(pet + (size_t)(mi * 16 + half * 8) * Ldim + ni * 8) = bb;
                }
            }
        }
        __syncthreads();
    }

    // reduce Z: within t-quad, then across the 4 n-warps via smem atomics
#pragma unroll
    for (int i = 0; i < 8; i++) {
        float z = zloc[i];
        z += __shfl_xor_sync(0xffffffffu, z, 1);
        z += __shfl_xor_sync(0xffffffffu, z, 2);
        if (t == 0) atomicAdd(&zsh[wm + (i >> 1) * 16 + (i & 1) * 8 + g], z);
    }
    __syncthreads();
    if (tid < 128) g_invZ[bh * Ldim + qbase + tid] = 1.f / zsh[tid];
}

// ======================================================================
// Pass B: w_k = sum_q e[bh][q][k] * invZ[bh][q]. CTA per (k-chunk 128, bh).
// ======================================================================
__global__ void __launch_bounds__(256) attn_passB_kernel()
{
    __shared__ float invz[Ldim];
    __shared__ float wsm[4][128];

    const int tid = threadIdx.x;
    const int bh = blockIdx.y;
    const int kbase = blockIdx.x * 128;

    for (int i = tid; i < Ldim; i += 256) invz[i] = g_invZ[bh * Ldim + i];
    __syncthreads();

    const int cp = tid & 63;     // column pair 0..63
    const int qoff = tid >> 6;   // 0..3
    const unsigned short* pe = g_e + ((size_t)bh * Ldim + qoff) * Ldim + kbase + cp * 2;

    float acc0 = 0.f, acc1 = 0.f;
#pragma unroll 8
    for (int q = qoff; q < Ldim; q += 4) {
        uint32_t raw = *(const uint32_t*)pe;
        float2 ev = __bfloat1622float2(*(const __nv_bfloat162*)&raw);
        float iz = invz[q];
        acc0 = fmaf(ev.x, iz, acc0);
        acc1 = fmaf(ev.y, iz, acc1);
        pe += 4 * Ldim;
    }
    wsm[qoff][cp * 2] = acc0;
    wsm[qoff][cp * 2 + 1] = acc1;
    __syncthreads();
    if (tid < 128) {
        float s = wsm[0][tid] + wsm[1][tid] + wsm[2][tid] + wsm[3][tid];
        g_w[bh * Ldim + kbase + tid] = s;
    }
}

// ======================================================================
// Zero g_ho, then GEMV: g_ho[b, h*64+d] = sum_k w[bh][k] * v[b,k][h*64+d]
// ======================================================================
__global__ void zero_ho_kernel()
{
    int i = blockIdx.x * blockDim.x + threadIdx.x;
    if (i < Bdim * Edim) g_ho[i] = 0.f;
}

__global__ void __launch_bounds__(256) gemv_ho_kernel()
{
    __shared__ float red[4][64];
    const int tid = threadIdx.x;
    const int bh = blockIdx.x;
    const int b = bh >> 4;
    const int h = bh & 15;
    const int kbase = blockIdx.y * 256;
    const int d = tid & 63;
    const int kq = tid >> 6;

    const float* vv = g_proj[2] + (size_t)(b * Ldim) * Edim + h * Ddim + d;
    const float* wp = g_w + bh * Ldim;

    float acc = 0.f;
#pragma unroll 8
    for (int k = kbase + kq; k < kbase + 256; k += 4)
        acc = fmaf(wp[k], vv[(size_t)k * Edim], acc);

    red[kq][d] = acc;
    __syncthreads();
    if (tid < 64) {
        float s = red[0][tid] + red[1][tid] + red[2][tid] + red[3][tid];
        atomicAdd(&g_ho[b * Edim + h * Ddim + tid], s);
    }
}

// ======================================================================
// Final: out[b, e'] = sum_e ho[b, e] * Wo[e', e]   (warp per output)
// ======================================================================
__global__ void __launch_bounds__(256) out_kernel(const float* __restrict__ Wo,
                                                  float* __restrict__ out)
{
    int gw = (blockIdx.x * blockDim.x + threadIdx.x) >> 5;
    int lane = threadIdx.x & 31;
    int b = gw >> 10;
    int ep = gw & 1023;
    const float* ho = &g_ho[(size_t)b * Edim];
    const float* wr = &Wo[(size_t)ep * Edim];
    float s = 0.f;
    for (int e = lane * 4; e < Edim; e += 128) {
        float4 w4 = *(const float4*)&wr[e];
        float4 h4 = *(const float4*)&ho[e];
        s = fmaf(w4.x, h4.x, s);
        s = fmaf(w4.y, h4.y, s);
        s = fmaf(w4.z, h4.z, s);
        s = fmaf(w4.w, h4.w, s);
    }
#pragma unroll
    for (int off = 16; off; off >>= 1) s += __shfl_xor_sync(0xffffffffu, s, off);
    if (lane == 0) out[(size_t)b * Edim + ep] = s;
}

// ======================================================================
extern "C" void kernel_launch(void* const* d_in, const int* in_sizes, int n_in,
                              void* d_out, int out_size)
{
    const float* Q = (const float*)d_in[0];
    const float* K = (const float*)d_in[1];
    const float* V = (const float*)d_in[2];
    const float* Wq = (const float*)d_in[3];
    const float* Wk = (const float*)d_in[4];
    const float* Wv = (const float*)d_in[5];
    const float* Wo = (const float*)d_in[6];
    float* out = (float*)d_out;

    cudaFuncSetAttribute(proj_mma_kernel, cudaFuncAttributeMaxDynamicSharedMemorySize, PJ_SMEM_BYTES);
    cudaFuncSetAttribute(attn_passA_kernel, cudaFuncAttributeMaxDynamicSharedMemorySize, A_SMEM_BYTES);

    proj_mma_kernel<<<dim3(NROWS / 128, Edim / 128, 3), 256, PJ_SMEM_BYTES>>>(Q, K, V, Wq, Wk, Wv);
    prep_sq_kernel<<<16384, 256>>>();
    attn_passA_kernel<<<dim3(Ldim / 128, NBH), 256, A_SMEM_BYTES>>>();
    attn_passB_kernel<<<dim3(Ldim / 128, NBH), 256>>>();
    zero_ho_kernel<<<2, 1024>>>();
    gemv_ho_kernel<<<dim3(NBH, Ldim / 256), 256>>>();
    out_kernel<<<256, 256>>>(Wo, out);
}